// round 8
// baseline (speedup 1.0000x reference)
#include <cuda_runtime.h>
#include <cuda_bf16.h>
#include <cstdint>

#define B_   32
#define CH_  512
#define N_   1024
#define D_   64
#define P_   8
#define BP_  256
#define O3_  1536

// Split-bf16 scratch written by QKV kernel, consumed by attention kernel.
// q, k' (=k+relpos): [bp][n][d];  v: pre-transposed [bp][d][n].
__device__ __nv_bfloat16 g_qh[(size_t)BP_ * N_ * D_];
__device__ __nv_bfloat16 g_ql[(size_t)BP_ * N_ * D_];
__device__ __nv_bfloat16 g_kh[(size_t)BP_ * N_ * D_];
__device__ __nv_bfloat16 g_kl[(size_t)BP_ * N_ * D_];
__device__ __nv_bfloat16 g_vth[(size_t)BP_ * D_ * N_];
__device__ __nv_bfloat16 g_vtl[(size_t)BP_ * D_ * N_];

__device__ __forceinline__ uint32_t pack2(float lo, float hi) {
    uint32_t r;
    asm("cvt.rn.bf16x2.f32 %0, %1, %2;" : "=r"(r) : "f"(hi), "f"(lo));
    return r;
}
// split x0,x1 into bf16 hi pair + bf16 residual pair
__device__ __forceinline__ void split2(float x0, float x1, uint32_t& hi, uint32_t& lo) {
    float h0 = __bfloat162float(__float2bfloat16(x0));
    float h1 = __bfloat162float(__float2bfloat16(x1));
    hi = pack2(h0, h1);
    lo = pack2(x0 - h0, x1 - h1);
}

__device__ __forceinline__ void mma16(float* c, const uint32_t* a, uint32_t b0, uint32_t b1) {
    asm("mma.sync.aligned.m16n8k16.row.col.f32.bf16.bf16.f32 "
        "{%0,%1,%2,%3}, {%4,%5,%6,%7}, {%8,%9}, {%0,%1,%2,%3};"
        : "+f"(c[0]), "+f"(c[1]), "+f"(c[2]), "+f"(c[3])
        : "r"(a[0]), "r"(a[1]), "r"(a[2]), "r"(a[3]), "r"(b0), "r"(b1));
}

// ---------------------------------------------------------------------------
// Kernel 1: QKV projection, split-bf16 m16n8k16 GEMM.
// C[o][n] = sum_c W[o][c] X[c][n].  Block 128(o) x 128(n), 8 warps 32x64.
// W tile natural [o][c] (A row-major); X tile natural [c][n], B-frags built
// from two u16 LDS + pack.  Epilogue emits split-bf16 scratch (V transposed,
// stored directly from fragments).
// ---------------------------------------------------------------------------
__global__ __launch_bounds__(256, 2) void qkv_kernel(
    const float* __restrict__ x,      // [B, 512, 1024]
    const float* __restrict__ w,      // [1536, 512]
    const float* __restrict__ h_pos,  // [32, 1, 512]
    const float* __restrict__ w_pos)  // [1, 32, 512]
{
    extern __shared__ char smraw[];
    __nv_bfloat16* Wh = (__nv_bfloat16*)smraw;            // [128][36]
    __nv_bfloat16* Wl = Wh + 128 * 36;
    unsigned short* Xh = (unsigned short*)(Wl + 128 * 36); // [32][136]
    unsigned short* Xl = Xh + 32 * 136;
    float* Cs = (float*)smraw;                             // epilogue reuse [128][132]

    const int tid  = threadIdx.x;
    const int lane = tid & 31;
    const int warp = tid >> 5;
    const int grp  = lane >> 2;
    const int t4   = lane & 3;
    const int ow   = (warp & 3) * 32;
    const int nw   = (warp >> 2) * 64;
    const int o0   = blockIdx.x * 128;
    const int n0   = blockIdx.y * 128;
    const int b    = blockIdx.z;
    const size_t xbase = (size_t)b * CH_ * N_;

    float acc[2][8][4];
#pragma unroll
    for (int m = 0; m < 2; m++)
#pragma unroll
        for (int nt = 0; nt < 8; nt++)
#pragma unroll
            for (int j = 0; j < 4; j++) acc[m][nt][j] = 0.f;

    for (int t = 0; t < 16; t++) {
        const int c0 = t * 32;
        __syncthreads();
        // W tile: 128 o x 32 c  (1024 float4)
#pragma unroll
        for (int i = 0; i < 4; i++) {
            const int fid = tid + i * 256;
            const int ol  = fid >> 3;
            const int cs  = (fid & 7) * 4;
            float4 wv = *(const float4*)&w[(size_t)(o0 + ol) * CH_ + c0 + cs];
            uint32_t h0, l0, h1, l1;
            split2(wv.x, wv.y, h0, l0);
            split2(wv.z, wv.w, h1, l1);
            *(uint32_t*)(Wh + ol * 36 + cs)     = h0;
            *(uint32_t*)(Wh + ol * 36 + cs + 2) = h1;
            *(uint32_t*)(Wl + ol * 36 + cs)     = l0;
            *(uint32_t*)(Wl + ol * 36 + cs + 2) = l1;
        }
        // X tile: 32 c x 128 n  (1024 float4)
#pragma unroll
        for (int i = 0; i < 4; i++) {
            const int fid = tid + i * 256;
            const int cl  = fid >> 5;
            const int ns  = (fid & 31) * 4;
            float4 xv = *(const float4*)&x[xbase + (size_t)(c0 + cl) * N_ + n0 + ns];
            uint32_t h0, l0, h1, l1;
            split2(xv.x, xv.y, h0, l0);
            split2(xv.z, xv.w, h1, l1);
            *(uint32_t*)(Xh + cl * 136 + ns)     = h0;
            *(uint32_t*)(Xh + cl * 136 + ns + 2) = h1;
            *(uint32_t*)(Xl + cl * 136 + ns)     = l0;
            *(uint32_t*)(Xl + cl * 136 + ns + 2) = l1;
        }
        __syncthreads();

#pragma unroll
        for (int kc = 0; kc < 2; kc++) {
            uint32_t ah[2][4], al[2][4];
#pragma unroll
            for (int m = 0; m < 2; m++) {
                const int base = (ow + m * 16 + grp) * 36 + kc * 16 + 2 * t4;
                ah[m][0] = *(const uint32_t*)(Wh + base);
                ah[m][1] = *(const uint32_t*)(Wh + base + 8 * 36);
                ah[m][2] = *(const uint32_t*)(Wh + base + 8);
                ah[m][3] = *(const uint32_t*)(Wh + base + 8 * 36 + 8);
                al[m][0] = *(const uint32_t*)(Wl + base);
                al[m][1] = *(const uint32_t*)(Wl + base + 8 * 36);
                al[m][2] = *(const uint32_t*)(Wl + base + 8);
                al[m][3] = *(const uint32_t*)(Wl + base + 8 * 36 + 8);
            }
#pragma unroll
            for (int nt = 0; nt < 8; nt++) {
                const int n = nw + nt * 8 + grp;
                const int c = kc * 16 + 2 * t4;
                uint32_t b0h = (uint32_t)Xh[c * 136 + n]       | ((uint32_t)Xh[(c + 1) * 136 + n] << 16);
                uint32_t b1h = (uint32_t)Xh[(c + 8) * 136 + n] | ((uint32_t)Xh[(c + 9) * 136 + n] << 16);
                uint32_t b0l = (uint32_t)Xl[c * 136 + n]       | ((uint32_t)Xl[(c + 1) * 136 + n] << 16);
                uint32_t b1l = (uint32_t)Xl[(c + 8) * 136 + n] | ((uint32_t)Xl[(c + 9) * 136 + n] << 16);
#pragma unroll
                for (int m = 0; m < 2; m++) {
                    mma16(acc[m][nt], ah[m], b0h, b1h);
                    mma16(acc[m][nt], ah[m], b0l, b1l);
                    mma16(acc[m][nt], al[m], b0h, b1h);
                }
            }
        }
    }

    const int bv = b;  // batch
    if (o0 >= 1024) {
        // V blocks: store transposed, straight from fragments (consecutive-n pairs).
#pragma unroll
        for (int m = 0; m < 2; m++) {
            const int ch = (o0 - 1024) + ow + m * 16 + grp;
            const int p  = ch >> 6;
#pragma unroll
            for (int nt = 0; nt < 8; nt++) {
                const int n = n0 + nw + nt * 8 + 2 * t4;
                uint32_t h, l;
                // row ch (dd = ch&63)
                split2(acc[m][nt][0], acc[m][nt][1], h, l);
                size_t idx = ((size_t)(bv * P_ + p) * D_ + (ch & 63)) * N_ + n;
                *(uint32_t*)&g_vth[idx] = h;
                *(uint32_t*)&g_vtl[idx] = l;
                // row ch+8
                split2(acc[m][nt][2], acc[m][nt][3], h, l);
                idx = ((size_t)(bv * P_ + p) * D_ + ((ch + 8) & 63)) * N_ + n;
                *(uint32_t*)&g_vth[idx] = h;
                *(uint32_t*)&g_vtl[idx] = l;
            }
        }
        return;
    }

    // Q/K blocks: fragments -> Cs [n][132] -> coalesced split-bf16 stores.
    __syncthreads();
#pragma unroll
    for (int m = 0; m < 2; m++)
#pragma unroll
        for (int nt = 0; nt < 8; nt++) {
            const int nn = nw + nt * 8 + 2 * t4;
            const int oo = ow + m * 16 + grp;
            Cs[(nn + 0) * 132 + oo]     = acc[m][nt][0];
            Cs[(nn + 1) * 132 + oo]     = acc[m][nt][1];
            Cs[(nn + 0) * 132 + oo + 8] = acc[m][nt][2];
            Cs[(nn + 1) * 132 + oo + 8] = acc[m][nt][3];
        }
    __syncthreads();

    const bool isk = (o0 >= 512);
    __nv_bfloat16* dh = isk ? g_kh : g_qh;
    __nv_bfloat16* dl = isk ? g_kl : g_ql;
#pragma unroll
    for (int j = 0; j < 16; j++) {
        const int fid = tid + j * 256;
        const int nl  = fid >> 5;
        const int os  = (fid & 31) * 4;
        float4 v4 = *(float4*)&Cs[nl * 132 + os];
        const int o  = o0 + os;
        const int ch = o & 511;
        const int n  = n0 + nl;
        if (isk) {
            const int hh = n >> 5, ww = n & 31;
            float4 hp = *(const float4*)&h_pos[hh * CH_ + ch];
            float4 wp = *(const float4*)&w_pos[ww * CH_ + ch];
            v4.x += hp.x + wp.x; v4.y += hp.y + wp.y;
            v4.z += hp.z + wp.z; v4.w += hp.w + wp.w;
        }
        const int p = ch >> 6, dd = ch & 63;
        const size_t base = ((size_t)(bv * P_ + p) * N_ + n) * D_ + dd;
        uint32_t h0, l0, h1, l1;
        split2(v4.x, v4.y, h0, l0);
        split2(v4.z, v4.w, h1, l1);
        *(uint32_t*)&dh[base]     = h0;
        *(uint32_t*)&dh[base + 2] = h1;
        *(uint32_t*)&dl[base]     = l0;
        *(uint32_t*)&dl[base + 2] = l1;
    }
}

// ---------------------------------------------------------------------------
// Kernel 2: flash attention, split-bf16 m16n8k16.
// Block = 8 warps = 128 q rows; warp owns 16 rows. 64-key tiles.
// Q frags straight from gmem; K/V tiles plain uint4 copies; P re-fragmented
// in registers (C-layout == A-layout).
// ---------------------------------------------------------------------------
__global__ __launch_bounds__(256, 2) void attn_kernel(float* __restrict__ out)
{
    extern __shared__ char smraw[];
    __nv_bfloat16* Kh = (__nv_bfloat16*)smraw;   // [64 key][72 d]
    __nv_bfloat16* Kl = Kh + 64 * 72;
    __nv_bfloat16* Vh = Kl + 64 * 72;            // [64 d][72 key]
    __nv_bfloat16* Vl = Vh + 64 * 72;
    float* stage = (float*)(smraw + 4 * 64 * 72 * 2);  // 8 warps x [16][68]

    const int tid  = threadIdx.x;
    const int lane = tid & 31;
    const int warp = tid >> 5;
    const int grp  = lane >> 2;
    const int t4   = lane & 3;
    const int bp   = blockIdx.y;
    const int q0   = blockIdx.x * 128 + warp * 16;
    float* Pw = stage + warp * (16 * 68);

    // Q fragments straight from split-bf16 scratch
    uint32_t qh[4][4], ql[4][4];
    {
        const __nv_bfloat16* qhp = g_qh + ((size_t)bp * N_ + q0) * D_;
        const __nv_bfloat16* qlp = g_ql + ((size_t)bp * N_ + q0) * D_;
#pragma unroll
        for (int ks = 0; ks < 4; ks++) {
            const size_t r0 = (size_t)grp * D_ + ks * 16 + 2 * t4;
            qh[ks][0] = *(const uint32_t*)(qhp + r0);
            qh[ks][1] = *(const uint32_t*)(qhp + r0 + 8 * D_);
            qh[ks][2] = *(const uint32_t*)(qhp + r0 + 8);
            qh[ks][3] = *(const uint32_t*)(qhp + r0 + 8 * D_ + 8);
            ql[ks][0] = *(const uint32_t*)(qlp + r0);
            ql[ks][1] = *(const uint32_t*)(qlp + r0 + 8 * D_);
            ql[ks][2] = *(const uint32_t*)(qlp + r0 + 8);
            ql[ks][3] = *(const uint32_t*)(qlp + r0 + 8 * D_ + 8);
        }
    }

    float o[8][4];
#pragma unroll
    for (int nt = 0; nt < 8; nt++)
#pragma unroll
        for (int j = 0; j < 4; j++) o[nt][j] = 0.f;
    float m0 = -1e30f, m1 = -1e30f, l0 = 0.f, l1 = 0.f;

    for (int kt = 0; kt < 16; kt++) {
        __syncthreads();
        {
            const __nv_bfloat16* khp = g_kh + ((size_t)bp * N_ + kt * 64) * D_;
            const __nv_bfloat16* klp = g_kl + ((size_t)bp * N_ + kt * 64) * D_;
            const __nv_bfloat16* vhp = g_vth + (size_t)bp * D_ * N_ + kt * 64;
            const __nv_bfloat16* vlp = g_vtl + (size_t)bp * D_ * N_ + kt * 64;
#pragma unroll
            for (int i = 0; i < 2; i++) {
                const int idx = tid + i * 256;       // 0..511
                const int row = idx >> 3;
                const int j   = idx & 7;
                *(uint4*)(Kh + row * 72 + j * 8) = *(const uint4*)(khp + row * D_ + j * 8);
                *(uint4*)(Kl + row * 72 + j * 8) = *(const uint4*)(klp + row * D_ + j * 8);
                *(uint4*)(Vh + row * 72 + j * 8) = *(const uint4*)(vhp + (size_t)row * N_ + j * 8);
                *(uint4*)(Vl + row * 72 + j * 8) = *(const uint4*)(vlp + (size_t)row * N_ + j * 8);
            }
        }
        __syncthreads();

        // S = Q K'^T
        float s[8][4];
#pragma unroll
        for (int nt = 0; nt < 8; nt++) {
            s[nt][0] = s[nt][1] = s[nt][2] = s[nt][3] = 0.f;
            const int key = nt * 8 + grp;
#pragma unroll
            for (int ks = 0; ks < 4; ks++) {
                uint32_t b0h = *(const uint32_t*)(Kh + key * 72 + ks * 16 + 2 * t4);
                uint32_t b1h = *(const uint32_t*)(Kh + key * 72 + ks * 16 + 8 + 2 * t4);
                uint32_t b0l = *(const uint32_t*)(Kl + key * 72 + ks * 16 + 2 * t4);
                uint32_t b1l = *(const uint32_t*)(Kl + key * 72 + ks * 16 + 8 + 2 * t4);
                mma16(s[nt], qh[ks], b0h, b1h);
                mma16(s[nt], qh[ks], b0l, b1l);
                mma16(s[nt], ql[ks], b0h, b1h);
            }
        }

        // online softmax (rows grp, grp+8)
        float mx0 = m0, mx1 = m1;
#pragma unroll
        for (int nt = 0; nt < 8; nt++) {
            mx0 = fmaxf(mx0, fmaxf(s[nt][0], s[nt][1]));
            mx1 = fmaxf(mx1, fmaxf(s[nt][2], s[nt][3]));
        }
        mx0 = fmaxf(mx0, __shfl_xor_sync(0xffffffffu, mx0, 1));
        mx0 = fmaxf(mx0, __shfl_xor_sync(0xffffffffu, mx0, 2));
        mx1 = fmaxf(mx1, __shfl_xor_sync(0xffffffffu, mx1, 1));
        mx1 = fmaxf(mx1, __shfl_xor_sync(0xffffffffu, mx1, 2));
        const float a0 = __expf(m0 - mx0), a1 = __expf(m1 - mx1);
        m0 = mx0; m1 = mx1;
        l0 *= a0; l1 *= a1;
        float ls0 = 0.f, ls1 = 0.f;
#pragma unroll
        for (int nt = 0; nt < 8; nt++) {
            o[nt][0] *= a0; o[nt][1] *= a0; o[nt][2] *= a1; o[nt][3] *= a1;
            s[nt][0] = __expf(s[nt][0] - m0); ls0 += s[nt][0];
            s[nt][1] = __expf(s[nt][1] - m0); ls0 += s[nt][1];
            s[nt][2] = __expf(s[nt][2] - m1); ls1 += s[nt][2];
            s[nt][3] = __expf(s[nt][3] - m1); ls1 += s[nt][3];
        }
        l0 += ls0; l1 += ls1;

        // P fragments from C-layout registers (no smem round trip)
        uint32_t ph[4][4], pl[4][4];
#pragma unroll
        for (int ks = 0; ks < 4; ks++) {
            split2(s[2 * ks][0],     s[2 * ks][1],     ph[ks][0], pl[ks][0]);
            split2(s[2 * ks][2],     s[2 * ks][3],     ph[ks][1], pl[ks][1]);
            split2(s[2 * ks + 1][0], s[2 * ks + 1][1], ph[ks][2], pl[ks][2]);
            split2(s[2 * ks + 1][2], s[2 * ks + 1][3], ph[ks][3], pl[ks][3]);
        }

        // O += P V
#pragma unroll
        for (int nt = 0; nt < 8; nt++) {
            const int d = nt * 8 + grp;
#pragma unroll
            for (int ks = 0; ks < 4; ks++) {
                uint32_t b0h = *(const uint32_t*)(Vh + d * 72 + ks * 16 + 2 * t4);
                uint32_t b1h = *(const uint32_t*)(Vh + d * 72 + ks * 16 + 8 + 2 * t4);
                uint32_t b0l = *(const uint32_t*)(Vl + d * 72 + ks * 16 + 2 * t4);
                uint32_t b1l = *(const uint32_t*)(Vl + d * 72 + ks * 16 + 8 + 2 * t4);
                mma16(o[nt], ph[ks], b0h, b1h);
                mma16(o[nt], ph[ks], b0l, b1l);
                mma16(o[nt], pl[ks], b0h, b1h);
            }
        }
    }

    // normalize + write out via per-warp staging transpose
    l0 += __shfl_xor_sync(0xffffffffu, l0, 1);
    l0 += __shfl_xor_sync(0xffffffffu, l0, 2);
    l1 += __shfl_xor_sync(0xffffffffu, l1, 1);
    l1 += __shfl_xor_sync(0xffffffffu, l1, 2);
    const float i0 = 1.f / l0, i1 = 1.f / l1;

#pragma unroll
    for (int nt = 0; nt < 8; nt++) {
        const int cc = nt * 8 + 2 * t4;
        Pw[grp * 68 + cc]           = o[nt][0] * i0;
        Pw[grp * 68 + cc + 1]       = o[nt][1] * i0;
        Pw[(grp + 8) * 68 + cc]     = o[nt][2] * i1;
        Pw[(grp + 8) * 68 + cc + 1] = o[nt][3] * i1;
    }
    __syncwarp();

    const int b = bp >> 3, p = bp & 7;
#pragma unroll
    for (int r = 0; r < 2; r++) {
        const int d = lane * 2 + r;
        float vals[16];
#pragma unroll
        for (int q = 0; q < 16; q++) vals[q] = Pw[q * 68 + d];
        float* ob = out + ((size_t)b * CH_ + p * D_ + d) * N_ + q0;
#pragma unroll
        for (int u = 0; u < 4; u++) {
            float4 v4 = {vals[u * 4], vals[u * 4 + 1], vals[u * 4 + 2], vals[u * 4 + 3]};
            *(float4*)&ob[u * 4] = v4;
        }
    }
}

extern "C" void kernel_launch(void* const* d_in, const int* in_sizes, int n_in,
                              void* d_out, int out_size)
{
    const float* x     = (const float*)d_in[0];
    const float* qkv_w = (const float*)d_in[1];
    const float* h_pos = (const float*)d_in[2];
    const float* w_pos = (const float*)d_in[3];
    float* out = (float*)d_out;

    const int smem1 = 128 * 132 * sizeof(float);                       // 67,584 (>= mainloop tiles)
    const int smem2 = 4 * 64 * 72 * 2 + 8 * 16 * 68 * (int)sizeof(float);  // 71,680
    cudaFuncSetAttribute(qkv_kernel, cudaFuncAttributeMaxDynamicSharedMemorySize, smem1);
    cudaFuncSetAttribute(attn_kernel, cudaFuncAttributeMaxDynamicSharedMemorySize, smem2);

    dim3 g1(O3_ / 128, N_ / 128, B_);   // 12 x 8 x 32
    qkv_kernel<<<g1, 256, smem1>>>(x, qkv_w, h_pos, w_pos);

    dim3 g2(N_ / 128, BP_);             // 8 x 256
    attn_kernel<<<g2, 256, smem2>>>(out);
}

// round 9
// speedup vs baseline: 1.0004x; 1.0004x over previous
#include <cuda_runtime.h>
#include <cuda_bf16.h>
#include <cstdint>

#define B_   32
#define CH_  512
#define N_   1024
#define D_   64
#define P_   8
#define BP_  256
#define O3_  1536

// Split-bf16 scratch written by QKV kernel, consumed by attention kernel.
// q, k' (=k+relpos): [bp][n][d];  v: pre-transposed [bp][d][n].
__device__ __nv_bfloat16 g_qh[(size_t)BP_ * N_ * D_];
__device__ __nv_bfloat16 g_ql[(size_t)BP_ * N_ * D_];
__device__ __nv_bfloat16 g_kh[(size_t)BP_ * N_ * D_];
__device__ __nv_bfloat16 g_kl[(size_t)BP_ * N_ * D_];
__device__ __nv_bfloat16 g_vth[(size_t)BP_ * D_ * N_];
__device__ __nv_bfloat16 g_vtl[(size_t)BP_ * D_ * N_];

__device__ __forceinline__ uint32_t pack2(float lo, float hi) {
    uint32_t r;
    asm("cvt.rn.bf16x2.f32 %0, %1, %2;" : "=r"(r) : "f"(hi), "f"(lo));
    return r;
}
// split x0,x1 into bf16 hi pair + bf16 residual pair
__device__ __forceinline__ void split2(float x0, float x1, uint32_t& hi, uint32_t& lo) {
    float h0 = __bfloat162float(__float2bfloat16(x0));
    float h1 = __bfloat162float(__float2bfloat16(x1));
    hi = pack2(h0, h1);
    lo = pack2(x0 - h0, x1 - h1);
}

__device__ __forceinline__ void mma16(float* c, const uint32_t* a, uint32_t b0, uint32_t b1) {
    asm("mma.sync.aligned.m16n8k16.row.col.f32.bf16.bf16.f32 "
        "{%0,%1,%2,%3}, {%4,%5,%6,%7}, {%8,%9}, {%0,%1,%2,%3};"
        : "+f"(c[0]), "+f"(c[1]), "+f"(c[2]), "+f"(c[3])
        : "r"(a[0]), "r"(a[1]), "r"(a[2]), "r"(a[3]), "r"(b0), "r"(b1));
}

// ---------------------------------------------------------------------------
// Kernel 1: QKV projection, split-bf16 m16n8k16 GEMM.
// C[o][n] = sum_c W[o][c] X[c][n].  Block 128(o) x 128(n), 8 warps 32x64.
// W tile natural [o][c] (A row-major); X tile natural [c][n], B-frags built
// from two u16 LDS + pack.  Epilogue emits split-bf16 scratch (V transposed,
// stored directly from fragments).
// ---------------------------------------------------------------------------
__global__ __launch_bounds__(256, 2) void qkv_kernel(
    const float* __restrict__ x,      // [B, 512, 1024]
    const float* __restrict__ w,      // [1536, 512]
    const float* __restrict__ h_pos,  // [32, 1, 512]
    const float* __restrict__ w_pos)  // [1, 32, 512]
{
    extern __shared__ char smraw[];
    __nv_bfloat16* Wh = (__nv_bfloat16*)smraw;            // [128][36]
    __nv_bfloat16* Wl = Wh + 128 * 36;
    unsigned short* Xh = (unsigned short*)(Wl + 128 * 36); // [32][136]
    unsigned short* Xl = Xh + 32 * 136;
    float* Cs = (float*)smraw;                             // epilogue reuse [128][132]

    const int tid  = threadIdx.x;
    const int lane = tid & 31;
    const int warp = tid >> 5;
    const int grp  = lane >> 2;
    const int t4   = lane & 3;
    const int ow   = (warp & 3) * 32;
    const int nw   = (warp >> 2) * 64;
    const int o0   = blockIdx.x * 128;
    const int n0   = blockIdx.y * 128;
    const int b    = blockIdx.z;
    const size_t xbase = (size_t)b * CH_ * N_;

    float acc[2][8][4];
#pragma unroll
    for (int m = 0; m < 2; m++)
#pragma unroll
        for (int nt = 0; nt < 8; nt++)
#pragma unroll
            for (int j = 0; j < 4; j++) acc[m][nt][j] = 0.f;

    for (int t = 0; t < 16; t++) {
        const int c0 = t * 32;
        __syncthreads();
        // W tile: 128 o x 32 c  (1024 float4)
#pragma unroll
        for (int i = 0; i < 4; i++) {
            const int fid = tid + i * 256;
            const int ol  = fid >> 3;
            const int cs  = (fid & 7) * 4;
            float4 wv = *(const float4*)&w[(size_t)(o0 + ol) * CH_ + c0 + cs];
            uint32_t h0, l0, h1, l1;
            split2(wv.x, wv.y, h0, l0);
            split2(wv.z, wv.w, h1, l1);
            *(uint32_t*)(Wh + ol * 36 + cs)     = h0;
            *(uint32_t*)(Wh + ol * 36 + cs + 2) = h1;
            *(uint32_t*)(Wl + ol * 36 + cs)     = l0;
            *(uint32_t*)(Wl + ol * 36 + cs + 2) = l1;
        }
        // X tile: 32 c x 128 n  (1024 float4)
#pragma unroll
        for (int i = 0; i < 4; i++) {
            const int fid = tid + i * 256;
            const int cl  = fid >> 5;
            const int ns  = (fid & 31) * 4;
            float4 xv = *(const float4*)&x[xbase + (size_t)(c0 + cl) * N_ + n0 + ns];
            uint32_t h0, l0, h1, l1;
            split2(xv.x, xv.y, h0, l0);
            split2(xv.z, xv.w, h1, l1);
            *(uint32_t*)(Xh + cl * 136 + ns)     = h0;
            *(uint32_t*)(Xh + cl * 136 + ns + 2) = h1;
            *(uint32_t*)(Xl + cl * 136 + ns)     = l0;
            *(uint32_t*)(Xl + cl * 136 + ns + 2) = l1;
        }
        __syncthreads();

#pragma unroll
        for (int kc = 0; kc < 2; kc++) {
            uint32_t ah[2][4], al[2][4];
#pragma unroll
            for (int m = 0; m < 2; m++) {
                const int base = (ow + m * 16 + grp) * 36 + kc * 16 + 2 * t4;
                ah[m][0] = *(const uint32_t*)(Wh + base);
                ah[m][1] = *(const uint32_t*)(Wh + base + 8 * 36);
                ah[m][2] = *(const uint32_t*)(Wh + base + 8);
                ah[m][3] = *(const uint32_t*)(Wh + base + 8 * 36 + 8);
                al[m][0] = *(const uint32_t*)(Wl + base);
                al[m][1] = *(const uint32_t*)(Wl + base + 8 * 36);
                al[m][2] = *(const uint32_t*)(Wl + base + 8);
                al[m][3] = *(const uint32_t*)(Wl + base + 8 * 36 + 8);
            }
#pragma unroll
            for (int nt = 0; nt < 8; nt++) {
                const int n = nw + nt * 8 + grp;
                const int c = kc * 16 + 2 * t4;
                uint32_t b0h = (uint32_t)Xh[c * 136 + n]       | ((uint32_t)Xh[(c + 1) * 136 + n] << 16);
                uint32_t b1h = (uint32_t)Xh[(c + 8) * 136 + n] | ((uint32_t)Xh[(c + 9) * 136 + n] << 16);
                uint32_t b0l = (uint32_t)Xl[c * 136 + n]       | ((uint32_t)Xl[(c + 1) * 136 + n] << 16);
                uint32_t b1l = (uint32_t)Xl[(c + 8) * 136 + n] | ((uint32_t)Xl[(c + 9) * 136 + n] << 16);
#pragma unroll
                for (int m = 0; m < 2; m++) {
                    mma16(acc[m][nt], ah[m], b0h, b1h);
                    mma16(acc[m][nt], ah[m], b0l, b1l);
                    mma16(acc[m][nt], al[m], b0h, b1h);
                }
            }
        }
    }

    const int bv = b;  // batch
    if (o0 >= 1024) {
        // V blocks: store transposed, straight from fragments (consecutive-n pairs).
#pragma unroll
        for (int m = 0; m < 2; m++) {
            const int ch = (o0 - 1024) + ow + m * 16 + grp;
            const int p  = ch >> 6;
#pragma unroll
            for (int nt = 0; nt < 8; nt++) {
                const int n = n0 + nw + nt * 8 + 2 * t4;
                uint32_t h, l;
                // row ch (dd = ch&63)
                split2(acc[m][nt][0], acc[m][nt][1], h, l);
                size_t idx = ((size_t)(bv * P_ + p) * D_ + (ch & 63)) * N_ + n;
                *(uint32_t*)&g_vth[idx] = h;
                *(uint32_t*)&g_vtl[idx] = l;
                // row ch+8
                split2(acc[m][nt][2], acc[m][nt][3], h, l);
                idx = ((size_t)(bv * P_ + p) * D_ + ((ch + 8) & 63)) * N_ + n;
                *(uint32_t*)&g_vth[idx] = h;
                *(uint32_t*)&g_vtl[idx] = l;
            }
        }
        return;
    }

    // Q/K blocks: fragments -> Cs [n][132] -> coalesced split-bf16 stores.
    __syncthreads();
#pragma unroll
    for (int m = 0; m < 2; m++)
#pragma unroll
        for (int nt = 0; nt < 8; nt++) {
            const int nn = nw + nt * 8 + 2 * t4;
            const int oo = ow + m * 16 + grp;
            Cs[(nn + 0) * 132 + oo]     = acc[m][nt][0];
            Cs[(nn + 1) * 132 + oo]     = acc[m][nt][1];
            Cs[(nn + 0) * 132 + oo + 8] = acc[m][nt][2];
            Cs[(nn + 1) * 132 + oo + 8] = acc[m][nt][3];
        }
    __syncthreads();

    const bool isk = (o0 >= 512);
    __nv_bfloat16* dh = isk ? g_kh : g_qh;
    __nv_bfloat16* dl = isk ? g_kl : g_ql;
#pragma unroll
    for (int j = 0; j < 16; j++) {
        const int fid = tid + j * 256;
        const int nl  = fid >> 5;
        const int os  = (fid & 31) * 4;
        float4 v4 = *(float4*)&Cs[nl * 132 + os];
        const int o  = o0 + os;
        const int ch = o & 511;
        const int n  = n0 + nl;
        if (isk) {
            const int hh = n >> 5, ww = n & 31;
            float4 hp = *(const float4*)&h_pos[hh * CH_ + ch];
            float4 wp = *(const float4*)&w_pos[ww * CH_ + ch];
            v4.x += hp.x + wp.x; v4.y += hp.y + wp.y;
            v4.z += hp.z + wp.z; v4.w += hp.w + wp.w;
        }
        const int p = ch >> 6, dd = ch & 63;
        const size_t base = ((size_t)(bv * P_ + p) * N_ + n) * D_ + dd;
        uint32_t h0, l0, h1, l1;
        split2(v4.x, v4.y, h0, l0);
        split2(v4.z, v4.w, h1, l1);
        *(uint32_t*)&dh[base]     = h0;
        *(uint32_t*)&dh[base + 2] = h1;
        *(uint32_t*)&dl[base]     = l0;
        *(uint32_t*)&dl[base + 2] = l1;
    }
}

// ---------------------------------------------------------------------------
// Kernel 2: flash attention, split-bf16 m16n8k16.
// Block = 8 warps = 128 q rows; warp owns 16 rows. 64-key tiles.
// Q frags straight from gmem; K/V tiles plain uint4 copies; P re-fragmented
// in registers (C-layout == A-layout).
// ---------------------------------------------------------------------------
__global__ __launch_bounds__(256, 2) void attn_kernel(float* __restrict__ out)
{
    extern __shared__ char smraw[];
    __nv_bfloat16* Kh = (__nv_bfloat16*)smraw;   // [64 key][72 d]
    __nv_bfloat16* Kl = Kh + 64 * 72;
    __nv_bfloat16* Vh = Kl + 64 * 72;            // [64 d][72 key]
    __nv_bfloat16* Vl = Vh + 64 * 72;
    float* stage = (float*)(smraw + 4 * 64 * 72 * 2);  // 8 warps x [16][68]

    const int tid  = threadIdx.x;
    const int lane = tid & 31;
    const int warp = tid >> 5;
    const int grp  = lane >> 2;
    const int t4   = lane & 3;
    const int bp   = blockIdx.y;
    const int q0   = blockIdx.x * 128 + warp * 16;
    float* Pw = stage + warp * (16 * 68);

    // Q fragments straight from split-bf16 scratch
    uint32_t qh[4][4], ql[4][4];
    {
        const __nv_bfloat16* qhp = g_qh + ((size_t)bp * N_ + q0) * D_;
        const __nv_bfloat16* qlp = g_ql + ((size_t)bp * N_ + q0) * D_;
#pragma unroll
        for (int ks = 0; ks < 4; ks++) {
            const size_t r0 = (size_t)grp * D_ + ks * 16 + 2 * t4;
            qh[ks][0] = *(const uint32_t*)(qhp + r0);
            qh[ks][1] = *(const uint32_t*)(qhp + r0 + 8 * D_);
            qh[ks][2] = *(const uint32_t*)(qhp + r0 + 8);
            qh[ks][3] = *(const uint32_t*)(qhp + r0 + 8 * D_ + 8);
            ql[ks][0] = *(const uint32_t*)(qlp + r0);
            ql[ks][1] = *(const uint32_t*)(qlp + r0 + 8 * D_);
            ql[ks][2] = *(const uint32_t*)(qlp + r0 + 8);
            ql[ks][3] = *(const uint32_t*)(qlp + r0 + 8 * D_ + 8);
        }
    }

    float o[8][4];
#pragma unroll
    for (int nt = 0; nt < 8; nt++)
#pragma unroll
        for (int j = 0; j < 4; j++) o[nt][j] = 0.f;
    float m0 = -1e30f, m1 = -1e30f, l0 = 0.f, l1 = 0.f;

    for (int kt = 0; kt < 16; kt++) {
        __syncthreads();
        {
            const __nv_bfloat16* khp = g_kh + ((size_t)bp * N_ + kt * 64) * D_;
            const __nv_bfloat16* klp = g_kl + ((size_t)bp * N_ + kt * 64) * D_;
            const __nv_bfloat16* vhp = g_vth + (size_t)bp * D_ * N_ + kt * 64;
            const __nv_bfloat16* vlp = g_vtl + (size_t)bp * D_ * N_ + kt * 64;
#pragma unroll
            for (int i = 0; i < 2; i++) {
                const int idx = tid + i * 256;       // 0..511
                const int row = idx >> 3;
                const int j   = idx & 7;
                *(uint4*)(Kh + row * 72 + j * 8) = *(const uint4*)(khp + row * D_ + j * 8);
                *(uint4*)(Kl + row * 72 + j * 8) = *(const uint4*)(klp + row * D_ + j * 8);
                *(uint4*)(Vh + row * 72 + j * 8) = *(const uint4*)(vhp + (size_t)row * N_ + j * 8);
                *(uint4*)(Vl + row * 72 + j * 8) = *(const uint4*)(vlp + (size_t)row * N_ + j * 8);
            }
        }
        __syncthreads();

        // S = Q K'^T
        float s[8][4];
#pragma unroll
        for (int nt = 0; nt < 8; nt++) {
            s[nt][0] = s[nt][1] = s[nt][2] = s[nt][3] = 0.f;
            const int key = nt * 8 + grp;
#pragma unroll
            for (int ks = 0; ks < 4; ks++) {
                uint32_t b0h = *(const uint32_t*)(Kh + key * 72 + ks * 16 + 2 * t4);
                uint32_t b1h = *(const uint32_t*)(Kh + key * 72 + ks * 16 + 8 + 2 * t4);
                uint32_t b0l = *(const uint32_t*)(Kl + key * 72 + ks * 16 + 2 * t4);
                uint32_t b1l = *(const uint32_t*)(Kl + key * 72 + ks * 16 + 8 + 2 * t4);
                mma16(s[nt], qh[ks], b0h, b1h);
                mma16(s[nt], qh[ks], b0l, b1l);
                mma16(s[nt], ql[ks], b0h, b1h);
            }
        }

        // online softmax (rows grp, grp+8)
        float mx0 = m0, mx1 = m1;
#pragma unroll
        for (int nt = 0; nt < 8; nt++) {
            mx0 = fmaxf(mx0, fmaxf(s[nt][0], s[nt][1]));
            mx1 = fmaxf(mx1, fmaxf(s[nt][2], s[nt][3]));
        }
        mx0 = fmaxf(mx0, __shfl_xor_sync(0xffffffffu, mx0, 1));
        mx0 = fmaxf(mx0, __shfl_xor_sync(0xffffffffu, mx0, 2));
        mx1 = fmaxf(mx1, __shfl_xor_sync(0xffffffffu, mx1, 1));
        mx1 = fmaxf(mx1, __shfl_xor_sync(0xffffffffu, mx1, 2));
        const float a0 = __expf(m0 - mx0), a1 = __expf(m1 - mx1);
        m0 = mx0; m1 = mx1;
        l0 *= a0; l1 *= a1;
        float ls0 = 0.f, ls1 = 0.f;
#pragma unroll
        for (int nt = 0; nt < 8; nt++) {
            o[nt][0] *= a0; o[nt][1] *= a0; o[nt][2] *= a1; o[nt][3] *= a1;
            s[nt][0] = __expf(s[nt][0] - m0); ls0 += s[nt][0];
            s[nt][1] = __expf(s[nt][1] - m0); ls0 += s[nt][1];
            s[nt][2] = __expf(s[nt][2] - m1); ls1 += s[nt][2];
            s[nt][3] = __expf(s[nt][3] - m1); ls1 += s[nt][3];
        }
        l0 += ls0; l1 += ls1;

        // P fragments from C-layout registers (no smem round trip)
        uint32_t ph[4][4], pl[4][4];
#pragma unroll
        for (int ks = 0; ks < 4; ks++) {
            split2(s[2 * ks][0],     s[2 * ks][1],     ph[ks][0], pl[ks][0]);
            split2(s[2 * ks][2],     s[2 * ks][3],     ph[ks][1], pl[ks][1]);
            split2(s[2 * ks + 1][0], s[2 * ks + 1][1], ph[ks][2], pl[ks][2]);
            split2(s[2 * ks + 1][2], s[2 * ks + 1][3], ph[ks][3], pl[ks][3]);
        }

        // O += P V
#pragma unroll
        for (int nt = 0; nt < 8; nt++) {
            const int d = nt * 8 + grp;
#pragma unroll
            for (int ks = 0; ks < 4; ks++) {
                uint32_t b0h = *(const uint32_t*)(Vh + d * 72 + ks * 16 + 2 * t4);
                uint32_t b1h = *(const uint32_t*)(Vh + d * 72 + ks * 16 + 8 + 2 * t4);
                uint32_t b0l = *(const uint32_t*)(Vl + d * 72 + ks * 16 + 2 * t4);
                uint32_t b1l = *(const uint32_t*)(Vl + d * 72 + ks * 16 + 8 + 2 * t4);
                mma16(o[nt], ph[ks], b0h, b1h);
                mma16(o[nt], ph[ks], b0l, b1l);
                mma16(o[nt], pl[ks], b0h, b1h);
            }
        }
    }

    // normalize + write out via per-warp staging transpose
    l0 += __shfl_xor_sync(0xffffffffu, l0, 1);
    l0 += __shfl_xor_sync(0xffffffffu, l0, 2);
    l1 += __shfl_xor_sync(0xffffffffu, l1, 1);
    l1 += __shfl_xor_sync(0xffffffffu, l1, 2);
    const float i0 = 1.f / l0, i1 = 1.f / l1;

#pragma unroll
    for (int nt = 0; nt < 8; nt++) {
        const int cc = nt * 8 + 2 * t4;
        Pw[grp * 68 + cc]           = o[nt][0] * i0;
        Pw[grp * 68 + cc + 1]       = o[nt][1] * i0;
        Pw[(grp + 8) * 68 + cc]     = o[nt][2] * i1;
        Pw[(grp + 8) * 68 + cc + 1] = o[nt][3] * i1;
    }
    __syncwarp();

    const int b = bp >> 3, p = bp & 7;
#pragma unroll
    for (int r = 0; r < 2; r++) {
        const int d = lane * 2 + r;
        float vals[16];
#pragma unroll
        for (int q = 0; q < 16; q++) vals[q] = Pw[q * 68 + d];
        float* ob = out + ((size_t)b * CH_ + p * D_ + d) * N_ + q0;
#pragma unroll
        for (int u = 0; u < 4; u++) {
            float4 v4 = {vals[u * 4], vals[u * 4 + 1], vals[u * 4 + 2], vals[u * 4 + 3]};
            *(float4*)&ob[u * 4] = v4;
        }
    }
}

extern "C" void kernel_launch(void* const* d_in, const int* in_sizes, int n_in,
                              void* d_out, int out_size)
{
    const float* x     = (const float*)d_in[0];
    const float* qkv_w = (const float*)d_in[1];
    const float* h_pos = (const float*)d_in[2];
    const float* w_pos = (const float*)d_in[3];
    float* out = (float*)d_out;

    const int smem1 = 128 * 132 * sizeof(float);                       // 67,584 (>= mainloop tiles)
    const int smem2 = 4 * 64 * 72 * 2 + 8 * 16 * 68 * (int)sizeof(float);  // 71,680
    cudaFuncSetAttribute(qkv_kernel, cudaFuncAttributeMaxDynamicSharedMemorySize, smem1);
    cudaFuncSetAttribute(attn_kernel, cudaFuncAttributeMaxDynamicSharedMemorySize, smem2);

    dim3 g1(O3_ / 128, N_ / 128, B_);   // 12 x 8 x 32
    qkv_kernel<<<g1, 256, smem1>>>(x, qkv_w, h_pos, w_pos);

    dim3 g2(N_ / 128, BP_);             // 8 x 256
    attn_kernel<<<g2, 256, smem2>>>(out);
}